// round 9
// baseline (speedup 1.0000x reference)
#include <cuda_runtime.h>
#include <cuda_fp16.h>
#include <math.h>
#include <cstdint>

#define N_   4
#define K_   8
#define H_   512
#define W_   512
#define C_   16
#define P_   1000000
#define HW_  (H_ * W_)
#define NPIX (N_ * HW_)

// Normalized weights below this contribute negligibly vs fp16 noise (2e-4).
#define W_EPS 1e-4f

// Transposed fp16 point cloud: [P][C], 32B per point. 32 MB -> L2 resident.
__device__ __align__(16) __half g_pt_h[(size_t)P_ * C_];

// ---------------------------------------------------------------------------
// Kernel 1: transpose + fp16-convert ptclds [C, P] -> g_pt_h [P, C].
// Vectorized: each thread handles 4 consecutive points via float4 reads
// (same bytes, 1/4 the instructions/wavefronts of the scalar version).
// ---------------------------------------------------------------------------
__global__ void transpose_ptclds_kernel(const float* __restrict__ pt) {
    int t = blockIdx.x * blockDim.x + threadIdx.x;   // float4 (4-point) index
    if (t >= P_ / 4) return;
    const float4* src = reinterpret_cast<const float4*>(pt);

#pragma unroll
    for (int hh = 0; hh < 2; hh++) {                 // channel halves
        float4 v[8];
#pragma unroll
        for (int c = 0; c < 8; c++)
            v[c] = __ldcs(src + (size_t)(hh * 8 + c) * (P_ / 4) + t);
        const float* vf = reinterpret_cast<const float*>(v);  // vf[c*4+e]

#pragma unroll
        for (int e = 0; e < 4; e++) {                // point within float4
            uint4 o;
            unsigned int* ow = reinterpret_cast<unsigned int*>(&o);
#pragma unroll
            for (int q = 0; q < 4; q++) {
                half2 h = __floats2half2_rn(vf[(2 * q + 0) * 4 + e],
                                            vf[(2 * q + 1) * 4 + e]);
                ow[q] = *reinterpret_cast<unsigned int*>(&h);
            }
            *reinterpret_cast<uint4*>(
                g_pt_h + (size_t)(4 * t + e) * C_ + hh * 8) = o;
        }
    }
}

// ---------------------------------------------------------------------------
// Kernel 2: pair-per-pixel compositor, batched predicated gathers (MLP=4),
// half2 accumulation (HFMA2) to cut registers -> occupancy back to ~85%
// while keeping the MLP (R8 lesson: 40 regs -> occ 67% ate the MLP win).
// ---------------------------------------------------------------------------
__global__ void __launch_bounds__(256, 7)
compositor_kernel(const int* __restrict__ frag,
                  const float* __restrict__ zbuf,
                  float* __restrict__ out) {
    int tid = threadIdx.x;
    int p   = tid >> 1;                // block-local pixel 0..127
    int j   = tid & 1;                 // pair lane (channel half / k half)

    int i  = blockIdx.x * 128 + p;     // global pixel; HW_ % 128 == 0
    int n  = i >> 18;                  // HW_ = 2^18
    int hw = i & (HW_ - 1);
    size_t base = (size_t)n * (K_ * HW_) + hw;

    // --- per-lane loads: k = 4j + r ---
    int   fr[4];
    float im[4];
#pragma unroll
    for (int r = 0; r < 4; r++) {
        size_t off = base + (size_t)(4 * j + r) * HW_;
        fr[r] = __ldcs(frag + off);
        float z = __ldcs(zbuf + off);
        if (z < 0.0f) z = -0.0001f;
        im[r] = __fdividef(1.0f, z + 1e-6f);
    }

    // --- distributed softmax across the pair ---
    float m = fmaxf(fmaxf(im[0], im[1]), fmaxf(im[2], im[3]));
    m = fmaxf(m, __shfl_xor_sync(0xffffffffu, m, 1));

    float w[4];
    float s = 0.0f;
#pragma unroll
    for (int r = 0; r < 4; r++) { w[r] = __expf(im[r] - m); s += w[r]; }
    s += __shfl_xor_sync(0xffffffffu, s, 1);
    float inv = __fdividef(1.0f, s);
#pragma unroll
    for (int r = 0; r < 4; r++) w[r] *= inv;

    const __half* tbl = g_pt_h + (size_t)(j * 8);

    // --- gather: 2 batches of 4 outstanding predicated 16B loads,
    //     accumulated in half2 (channels 2h, 2h+1 per acc[h]) ---
    half2 acc[4];
#pragma unroll
    for (int h = 0; h < 4; h++) acc[h] = __float2half2_rn(0.0f);

#pragma unroll
    for (int b = 0; b < 2; b++) {
        int src = (tid & ~1) | b;              // pair lane owning this batch's k
        unsigned int vd[4][4];

        // Issue 4 independent predicated loads (k = 4b + r).
#pragma unroll
        for (int r = 0; r < 4; r++) {
            float wk = __shfl_sync(0xffffffffu, w[r],  src);
            int   fk = __shfl_sync(0xffffffffu, fr[r], src);
            const __half* pp = tbl + (size_t)fk * C_;
            asm volatile(
                "{\n\t"
                ".reg .pred p;\n\t"
                "setp.ge.f32 p, %4, %5;\n\t"
                "mov.b32 %0, 0;\n\t"
                "mov.b32 %1, 0;\n\t"
                "mov.b32 %2, 0;\n\t"
                "mov.b32 %3, 0;\n\t"
                "@p ld.global.nc.v4.b32 {%0,%1,%2,%3}, [%6];\n\t"
                "}"
                : "=r"(vd[r][0]), "=r"(vd[r][1]), "=r"(vd[r][2]), "=r"(vd[r][3])
                : "f"(wk), "f"(W_EPS), "l"(pp));
        }

        // Consume with HFMA2 (wk broadcast to half2; zeros contribute 0).
#pragma unroll
        for (int r = 0; r < 4; r++) {
            float wk = __shfl_sync(0xffffffffu, w[r], src);
            half2 wk2 = __float2half2_rn(wk);
#pragma unroll
            for (int h = 0; h < 4; h++) {
                half2 v = *reinterpret_cast<half2*>(&vd[r][h]);
                acc[h] = __hfma2(wk2, v, acc[h]);
            }
        }
    }

    // --- direct stores: lane j writes channels 8j..8j+7 (fp32) ---
    size_t ob = (size_t)n * (C_ * HW_) + (size_t)(j * 8) * HW_ + hw;
#pragma unroll
    for (int h = 0; h < 4; h++) {
        float2 f = __half22float2(acc[h]);
        __stcs(out + ob + (size_t)(2 * h + 0) * HW_, f.x);
        __stcs(out + ob + (size_t)(2 * h + 1) * HW_, f.y);
    }
}

extern "C" void kernel_launch(void* const* d_in, const int* in_sizes, int n_in,
                              void* d_out, int out_size) {
    const int*   fragments = (const int*)d_in[0];
    const float* zbuf      = (const float*)d_in[1];
    const float* ptclds    = (const float*)d_in[2];
    float*       out       = (float*)d_out;

    (void)in_sizes; (void)n_in; (void)out_size;

    {
        int threads = 256;
        int blocks  = (P_ / 4 + threads - 1) / threads;
        transpose_ptclds_kernel<<<blocks, threads>>>(ptclds);
    }
    {
        int threads = 256;
        int blocks  = NPIX / 128;      // 128 pixels per block (pair-per-pixel)
        compositor_kernel<<<blocks, threads>>>(fragments, zbuf, out);
    }
}

// round 10
// speedup vs baseline: 1.0762x; 1.0762x over previous
#include <cuda_runtime.h>
#include <cuda_fp16.h>
#include <math.h>
#include <cstdint>

#define N_   4
#define K_   8
#define H_   512
#define W_   512
#define C_   16
#define P_   1000000
#define HW_  (H_ * W_)
#define NPIX (N_ * HW_)

// Normalized weights below this contribute negligibly vs fp16 noise.
#define W_EPS 1e-4f

// Transposed fp16 point cloud: [P][C], 32B per point. 32 MB -> L2 resident.
__device__ __align__(16) __half g_pt_h[(size_t)P_ * C_];

// ---------------------------------------------------------------------------
// Kernel 1: transpose + fp16-convert ptclds [C, P] -> g_pt_h [P, C].
// Scalar per-point version (R8): measured 15.2us, near the 96MB DRAM floor.
// (R9's 4-point float4 variant regressed to 20us: 32+ live regs -> spills.)
// ---------------------------------------------------------------------------
__global__ void transpose_ptclds_kernel(const float* __restrict__ pt) {
    int p = blockIdx.x * blockDim.x + threadIdx.x;
    if (p >= P_) return;
    uint4* dst = reinterpret_cast<uint4*>(g_pt_h + (size_t)p * C_);
#pragma unroll
    for (int hh = 0; hh < 2; hh++) {          // 8 channels per 16B store
        uint4 o;
        unsigned int* ow = reinterpret_cast<unsigned int*>(&o);
#pragma unroll
        for (int j = 0; j < 4; j++) {
            int c0 = hh * 8 + j * 2;
            float a = __ldcs(pt + (size_t)(c0 + 0) * P_ + p);
            float b = __ldcs(pt + (size_t)(c0 + 1) * P_ + p);
            half2 h = __floats2half2_rn(a, b);
            ow[j] = *reinterpret_cast<unsigned int*>(&h);
        }
        dst[hh] = o;
    }
}

// ---------------------------------------------------------------------------
// Kernel 2: pair-per-pixel compositor, batched predicated gathers (MLP=4),
// half2 accumulation (HFMA2). regs=32, occ ~88% (R9 measured).
// ---------------------------------------------------------------------------
__global__ void __launch_bounds__(256, 7)
compositor_kernel(const int* __restrict__ frag,
                  const float* __restrict__ zbuf,
                  float* __restrict__ out) {
    int tid = threadIdx.x;
    int p   = tid >> 1;                // block-local pixel 0..127
    int j   = tid & 1;                 // pair lane (channel half / k half)

    int i  = blockIdx.x * 128 + p;     // global pixel; HW_ % 128 == 0
    int n  = i >> 18;                  // HW_ = 2^18
    int hw = i & (HW_ - 1);
    size_t base = (size_t)n * (K_ * HW_) + hw;

    // --- per-lane loads: k = 4j + r ---
    int   fr[4];
    float im[4];
#pragma unroll
    for (int r = 0; r < 4; r++) {
        size_t off = base + (size_t)(4 * j + r) * HW_;
        fr[r] = __ldcs(frag + off);
        float z = __ldcs(zbuf + off);
        if (z < 0.0f) z = -0.0001f;
        im[r] = __fdividef(1.0f, z + 1e-6f);
    }

    // --- distributed softmax across the pair ---
    float m = fmaxf(fmaxf(im[0], im[1]), fmaxf(im[2], im[3]));
    m = fmaxf(m, __shfl_xor_sync(0xffffffffu, m, 1));

    float w[4];
    float s = 0.0f;
#pragma unroll
    for (int r = 0; r < 4; r++) { w[r] = __expf(im[r] - m); s += w[r]; }
    s += __shfl_xor_sync(0xffffffffu, s, 1);
    float inv = __fdividef(1.0f, s);
#pragma unroll
    for (int r = 0; r < 4; r++) w[r] *= inv;

    const __half* tbl = g_pt_h + (size_t)(j * 8);

    // --- gather: 2 batches of 4 outstanding predicated 16B loads,
    //     accumulated in half2 (channels 2h, 2h+1 per acc[h]) ---
    half2 acc[4];
#pragma unroll
    for (int h = 0; h < 4; h++) acc[h] = __float2half2_rn(0.0f);

#pragma unroll
    for (int b = 0; b < 2; b++) {
        int src = (tid & ~1) | b;              // pair lane owning this batch's k
        unsigned int vd[4][4];
        float wks[4];

        // Issue 4 independent predicated loads (k = 4b + r).
#pragma unroll
        for (int r = 0; r < 4; r++) {
            wks[r]  = __shfl_sync(0xffffffffu, w[r],  src);
            int fk  = __shfl_sync(0xffffffffu, fr[r], src);
            const __half* pp = tbl + (size_t)fk * C_;
            asm volatile(
                "{\n\t"
                ".reg .pred p;\n\t"
                "setp.ge.f32 p, %4, %5;\n\t"
                "mov.b32 %0, 0;\n\t"
                "mov.b32 %1, 0;\n\t"
                "mov.b32 %2, 0;\n\t"
                "mov.b32 %3, 0;\n\t"
                "@p ld.global.nc.v4.b32 {%0,%1,%2,%3}, [%6];\n\t"
                "}"
                : "=r"(vd[r][0]), "=r"(vd[r][1]), "=r"(vd[r][2]), "=r"(vd[r][3])
                : "f"(wks[r]), "f"(W_EPS), "l"(pp));
        }

        // Consume with HFMA2 (wk broadcast to half2; zeros contribute 0).
#pragma unroll
        for (int r = 0; r < 4; r++) {
            half2 wk2 = __float2half2_rn(wks[r]);
#pragma unroll
            for (int h = 0; h < 4; h++) {
                half2 v = *reinterpret_cast<half2*>(&vd[r][h]);
                acc[h] = __hfma2(wk2, v, acc[h]);
            }
        }
    }

    // --- direct stores: lane j writes channels 8j..8j+7 (fp32) ---
    size_t ob = (size_t)n * (C_ * HW_) + (size_t)(j * 8) * HW_ + hw;
#pragma unroll
    for (int h = 0; h < 4; h++) {
        float2 f = __half22float2(acc[h]);
        __stcs(out + ob + (size_t)(2 * h + 0) * HW_, f.x);
        __stcs(out + ob + (size_t)(2 * h + 1) * HW_, f.y);
    }
}

extern "C" void kernel_launch(void* const* d_in, const int* in_sizes, int n_in,
                              void* d_out, int out_size) {
    const int*   fragments = (const int*)d_in[0];
    const float* zbuf      = (const float*)d_in[1];
    const float* ptclds    = (const float*)d_in[2];
    float*       out       = (float*)d_out;

    (void)in_sizes; (void)n_in; (void)out_size;

    {
        int threads = 256;
        int blocks  = (P_ + threads - 1) / threads;
        transpose_ptclds_kernel<<<blocks, threads>>>(ptclds);
    }
    {
        int threads = 256;
        int blocks  = NPIX / 128;      // 128 pixels per block (pair-per-pixel)
        compositor_kernel<<<blocks, threads>>>(fragments, zbuf, out);
    }
}